// round 10
// baseline (speedup 1.0000x reference)
#include <cuda_runtime.h>
#include <cuda_bf16.h>
#include <cstdint>

#define N_NODES 50000
#define N_EDGES 800000
#define IN_CH   128
#define H_CH    128
#define NCAT    256   // W_l and W_r stacked

// ---------------- device scratch ----------------
__device__ float d_w[NCAT * IN_CH];            // packed [W_l; W_r], row-major [256,128]
__device__ float d_g[N_NODES * NCAT];          // row n: [g_l(128) | g_r(128)]
__device__ int   d_count[N_NODES];
__device__ int   d_start[N_NODES + 1];
__device__ int   d_cursor[N_NODES];
__device__ int   d_src_sorted[N_EDGES];
__device__ float d_env_sorted[N_EDGES];
__device__ int   d_bsum[128];                  // per-block sums for multi-block scan

// ---------------- f32x2 helpers ----------------
__device__ __forceinline__ unsigned long long pack2(float lo, float hi) {
    unsigned long long r;
    asm("mov.b64 %0, {%1, %2};" : "=l"(r) : "f"(lo), "f"(hi));
    return r;
}
__device__ __forceinline__ void unpack2(unsigned long long v, float& lo, float& hi) {
    asm("mov.b64 {%0, %1}, %2;" : "=f"(lo), "=f"(hi) : "l"(v));
}
__device__ __forceinline__ unsigned long long fma2(unsigned long long a,
                                                   unsigned long long b,
                                                   unsigned long long c) {
    unsigned long long d;
    asm("fma.rn.f32x2 %0, %1, %2, %3;" : "=l"(d) : "l"(a), "l"(b), "l"(c));
    return d;
}
__device__ __forceinline__ float tanh_approx(float x) {
    float y;
    asm("tanh.approx.f32 %0, %1;" : "=f"(y) : "f"(x));
    return y;
}
// silu via tanh: sigmoid(t) = 0.5 + 0.5*tanh(0.5*t)  -> 1 MUFU per channel
__device__ __forceinline__ float silu_t(float t) {
    float th = tanh_approx(0.5f * t);
    return t * fmaf(0.5f, th, 0.5f);
}

// ---------------- kernel 1: pack W + zero counts (merged) ----------------
__global__ void prep_kernel(const float* __restrict__ Wl, const float* __restrict__ Wr) {
    int i = blockIdx.x * blockDim.x + threadIdx.x;
    if (i < H_CH * IN_CH) {
        d_w[i] = Wl[i];
        d_w[H_CH * IN_CH + i] = Wr[i];
    }
    if (i < N_NODES) d_count[i] = 0;
}

// ---------------- kernel 2: SGEMM via FFMA2 (BM=BN=64, 4x4) ----------------
#define BM 64
#define BN 64
#define BK 16
#define PAD 68

__global__ __launch_bounds__(256) void gemm_kernel(const float* __restrict__ q) {
    __shared__ float As[BK][PAD];  // As[k][m]
    __shared__ float Bs[BK][PAD];  // Bs[k][n]

    const int block_m = blockIdx.x * BM;
    const int block_n = blockIdx.y * BN;
    const int tid = threadIdx.x;
    const int tn = tid & 15;
    const int tm = tid >> 4;

    const int lrow  = tid >> 2;
    const int lcol4 = (tid & 3) << 2;

    unsigned long long acc2[4][2];
#pragma unroll
    for (int i = 0; i < 4; i++) { acc2[i][0] = 0ULL; acc2[i][1] = 0ULL; }

#pragma unroll
    for (int k0 = 0; k0 < IN_CH; k0 += BK) {
        float4 av = make_float4(0.f, 0.f, 0.f, 0.f);
        int arow = block_m + lrow;
        if (arow < N_NODES)
            av = *reinterpret_cast<const float4*>(&q[arow * IN_CH + k0 + lcol4]);
        As[lcol4 + 0][lrow] = av.x;
        As[lcol4 + 1][lrow] = av.y;
        As[lcol4 + 2][lrow] = av.z;
        As[lcol4 + 3][lrow] = av.w;
        float4 bv = *reinterpret_cast<const float4*>(&d_w[(block_n + lrow) * IN_CH + k0 + lcol4]);
        Bs[lcol4 + 0][lrow] = bv.x;
        Bs[lcol4 + 1][lrow] = bv.y;
        Bs[lcol4 + 2][lrow] = bv.z;
        Bs[lcol4 + 3][lrow] = bv.w;
        __syncthreads();

#pragma unroll
        for (int kk = 0; kk < BK; kk++) {
            float4 a = *reinterpret_cast<const float4*>(&As[kk][tm << 2]);
            float4 b = *reinterpret_cast<const float4*>(&Bs[kk][tn << 2]);
            unsigned long long bp0 = pack2(b.x, b.y);
            unsigned long long bp1 = pack2(b.z, b.w);
            float ar[4] = {a.x, a.y, a.z, a.w};
#pragma unroll
            for (int i = 0; i < 4; i++) {
                unsigned long long ad = pack2(ar[i], ar[i]);
                acc2[i][0] = fma2(ad, bp0, acc2[i][0]);
                acc2[i][1] = fma2(ad, bp1, acc2[i][1]);
            }
        }
        __syncthreads();
    }

#pragma unroll
    for (int i = 0; i < 4; i++) {
        int row = block_m + (tm << 2) + i;
        if (row < N_NODES) {
            float o0, o1, o2, o3;
            unpack2(acc2[i][0], o0, o1);
            unpack2(acc2[i][1], o2, o3);
            *reinterpret_cast<float4*>(&d_g[row * NCAT + block_n + (tn << 2)]) =
                make_float4(o0, o1, o2, o3);
        }
    }
}

// ---------------- kernel 3: histogram of dst (4 edges/thread) ----------------
__global__ void hist_kernel(const int* __restrict__ ei) {
    int t = blockIdx.x * blockDim.x + threadIdx.x;
    int i4 = t * 4;
    if (i4 < N_EDGES) {
        int4 d = *reinterpret_cast<const int4*>(&ei[N_EDGES + i4]);
        atomicAdd(&d_count[d.x], 1);
        atomicAdd(&d_count[d.y], 1);
        atomicAdd(&d_count[d.z], 1);
        atomicAdd(&d_count[d.w], 1);
    }
}

// ---------------- multi-block scan: 3 phases ----------------
#define SCANA_T 512
#define SCAN_NBLK ((N_NODES + SCANA_T - 1) / SCANA_T)   // 98

__global__ __launch_bounds__(SCANA_T) void scanA_kernel() {
    __shared__ int wt[16];
    int tid = threadIdx.x;
    int lane = tid & 31;
    int wid = tid >> 5;
    int idx = blockIdx.x * SCANA_T + tid;

    int v = (idx < N_NODES) ? d_count[idx] : 0;
    int ws = v;
#pragma unroll
    for (int off = 1; off < 32; off <<= 1) {
        int y = __shfl_up_sync(0xffffffffu, ws, off);
        if (lane >= off) ws += y;
    }
    if (lane == 31) wt[wid] = ws;
    __syncthreads();
    if (tid < 16) {
        int y = wt[tid];
#pragma unroll
        for (int off = 1; off < 16; off <<= 1) {
            int z = __shfl_up_sync(0x0000ffffu, y, off);
            if (tid >= off) y += z;
        }
        wt[tid] = y;
    }
    __syncthreads();
    int incl = ws + (wid ? wt[wid - 1] : 0);
    if (idx < N_NODES) d_start[idx] = incl - v;
    if (tid == SCANA_T - 1) d_bsum[blockIdx.x] = incl;
}

__global__ __launch_bounds__(128) void scanB_kernel() {
    __shared__ int wt[4];
    int tid = threadIdx.x;
    int lane = tid & 31;
    int wid = tid >> 5;
    int v = (tid < SCAN_NBLK) ? d_bsum[tid] : 0;
    int ws = v;
#pragma unroll
    for (int off = 1; off < 32; off <<= 1) {
        int y = __shfl_up_sync(0xffffffffu, ws, off);
        if (lane >= off) ws += y;
    }
    if (lane == 31) wt[wid] = ws;
    __syncthreads();
    if (tid < 4) {
        int y = wt[tid];
#pragma unroll
        for (int off = 1; off < 4; off <<= 1) {
            int z = __shfl_up_sync(0x0000000fu, y, off);
            if (tid >= off) y += z;
        }
        wt[tid] = y;
    }
    __syncthreads();
    int incl = ws + (wid ? wt[wid - 1] : 0);
    if (tid < SCAN_NBLK) d_bsum[tid] = incl - v;
    if (tid == 127) d_start[N_NODES] = incl;
}

__global__ __launch_bounds__(SCANA_T) void scanC_kernel() {
    int idx = blockIdx.x * SCANA_T + threadIdx.x;
    if (idx < N_NODES) {
        int e = d_start[idx] + d_bsum[blockIdx.x];
        d_start[idx]  = e;
        d_cursor[idx] = e;
    }
}

// ---------------- kernel 5: scatter edges (4 edges/thread, bounds-guarded) ----------------
__global__ void scatter_kernel(const int* __restrict__ ei,
                               const float* __restrict__ envelope) {
    int t = blockIdx.x * blockDim.x + threadIdx.x;
    int i4 = t * 4;
    if (i4 < N_EDGES) {
        int4   s = *reinterpret_cast<const int4*>(&ei[i4]);
        int4   d = *reinterpret_cast<const int4*>(&ei[N_EDGES + i4]);
        float4 e = *reinterpret_cast<const float4*>(&envelope[i4]);
        int p0 = atomicAdd(&d_cursor[d.x], 1);
        if ((unsigned)p0 < N_EDGES) { d_src_sorted[p0] = s.x; d_env_sorted[p0] = e.x; }
        int p1 = atomicAdd(&d_cursor[d.y], 1);
        if ((unsigned)p1 < N_EDGES) { d_src_sorted[p1] = s.y; d_env_sorted[p1] = e.y; }
        int p2 = atomicAdd(&d_cursor[d.z], 1);
        if ((unsigned)p2 < N_EDGES) { d_src_sorted[p2] = s.z; d_env_sorted[p2] = e.z; }
        int p3 = atomicAdd(&d_cursor[d.w], 1);
        if ((unsigned)p3 < N_EDGES) { d_src_sorted[p3] = s.w; d_env_sorted[p3] = e.w; }
    }
}

// ---------------- kernel 6: per-node softmax + aggregation ----------------
// Half-warp layout: lanes 0-15 = edge A, lanes 16-31 = edge B; 8 channels/lane.
__global__ __launch_bounds__(256) void out_kernel(const float* __restrict__ attn_w,
                                                  float* __restrict__ out) {
    int warp_id = (blockIdx.x * blockDim.x + threadIdx.x) >> 5;
    if (warp_id >= N_NODES) return;
    int lane = threadIdx.x & 31;
    int half = lane >> 4;          // 0 or 1
    int ch8  = (lane & 15) << 3;   // channel base: 0,8,...,120
    int n = warp_id;

    const float4* grp = reinterpret_cast<const float4*>(&d_g[n * NCAT + H_CH + ch8]);
    float4 gr0 = grp[0], gr1 = grp[1];
    const float4* awp = reinterpret_cast<const float4*>(&attn_w[ch8]);
    float4 aw0 = awp[0], aw1 = awp[1];

    float acc[8] = {0.f, 0.f, 0.f, 0.f, 0.f, 0.f, 0.f, 0.f};
    float denom = 0.f;

    int js = d_start[n];
    int je = d_start[n + 1];
    js = (js < 0) ? 0 : js;
    je = (je > N_EDGES) ? N_EDGES : je;

#pragma unroll 2
    for (int j = js; j < je; j += 2) {
        int idx = j + half;
        bool valid = idx < je;
        int jj = valid ? idx : (je - 1);
        int src   = d_src_sorted[jj];
        float env = d_env_sorted[jj];

        const float4* gp = reinterpret_cast<const float4*>(&d_g[src * NCAT + ch8]);
        float4 g0 = gp[0], g1 = gp[1];

        float p = silu_t(g0.x + gr0.x) * aw0.x
                + silu_t(g0.y + gr0.y) * aw0.y
                + silu_t(g0.z + gr0.z) * aw0.z
                + silu_t(g0.w + gr0.w) * aw0.w
                + silu_t(g1.x + gr1.x) * aw1.x
                + silu_t(g1.y + gr1.y) * aw1.y
                + silu_t(g1.z + gr1.z) * aw1.z
                + silu_t(g1.w + gr1.w) * aw1.w;

        // butterfly within 16-lane half (xor offsets never cross bit 4)
        p += __shfl_xor_sync(0xffffffffu, p, 1);
        p += __shfl_xor_sync(0xffffffffu, p, 2);
        p += __shfl_xor_sync(0xffffffffu, p, 4);
        p += __shfl_xor_sync(0xffffffffu, p, 8);

        float ex = __expf(p) * (env + 1e-7f);
        if (!valid) ex = 0.f;

        denom  += ex;
        acc[0] += ex * g0.x;
        acc[1] += ex * g0.y;
        acc[2] += ex * g0.z;
        acc[3] += ex * g0.w;
        acc[4] += ex * g1.x;
        acc[5] += ex * g1.y;
        acc[6] += ex * g1.z;
        acc[7] += ex * g1.w;
    }

    // combine the two halves (lane L <-> lane L+16 hold the same channels)
    denom += __shfl_xor_sync(0xffffffffu, denom, 16);
#pragma unroll
    for (int c = 0; c < 8; c++)
        acc[c] += __shfl_xor_sync(0xffffffffu, acc[c], 16);

    float inv = (denom > 0.f) ? (1.f / denom) : 0.f;
    if (half == 0) {
        float* op = &out[n * H_CH + ch8];
        *reinterpret_cast<float4*>(op) =
            make_float4(acc[0] * inv, acc[1] * inv, acc[2] * inv, acc[3] * inv);
        *reinterpret_cast<float4*>(op + 4) =
            make_float4(acc[4] * inv, acc[5] * inv, acc[6] * inv, acc[7] * inv);
    }
}

// ---------------- launch ----------------
extern "C" void kernel_launch(void* const* d_in, const int* in_sizes, int n_in,
                              void* d_out, int out_size) {
    const float* q        = (const float*)d_in[0];
    const float* envelope = (const float*)d_in[3];
    const float* W_l      = (const float*)d_in[4];
    const float* W_r      = (const float*)d_in[5];
    const float* attn_w   = (const float*)d_in[6];
    const int*   ei       = (const int*)d_in[7];
    float* out = (float*)d_out;

    prep_kernel<<<(N_NODES + 255) / 256, 256>>>(W_l, W_r);

    dim3 ggrid((N_NODES + BM - 1) / BM, NCAT / BN);
    gemm_kernel<<<ggrid, 256>>>(q);

    hist_kernel<<<(N_EDGES / 4 + 255) / 256, 256>>>(ei);
    scanA_kernel<<<SCAN_NBLK, SCANA_T>>>();
    scanB_kernel<<<1, 128>>>();
    scanC_kernel<<<SCAN_NBLK, SCANA_T>>>();
    scatter_kernel<<<(N_EDGES / 4 + 255) / 256, 256>>>(ei, envelope);

    int total_threads = N_NODES * 32;
    out_kernel<<<(total_threads + 255) / 256, 256>>>(attn_w, out);
}

// round 11
// speedup vs baseline: 1.1175x; 1.1175x over previous
#include <cuda_runtime.h>
#include <cuda_bf16.h>
#include <cstdint>

#define N_NODES 50000
#define N_EDGES 800000
#define IN_CH   128
#define H_CH    128
#define NCAT    256

// ---------------- device scratch ----------------
__device__ float d_g[N_NODES * NCAT];          // row n: [g_l(128) | g_r(128)]
__device__ int   d_count[N_NODES];             // invariant: zero at entry (scanC re-zeroes)
__device__ int   d_start[N_NODES + 1];
__device__ int   d_cursor[N_NODES];
__device__ int   d_src_sorted[N_EDGES];
__device__ float d_env_sorted[N_EDGES];
__device__ int   d_bsum[128];

// ---------------- helpers ----------------
__device__ __forceinline__ unsigned long long pack2(float lo, float hi) {
    unsigned long long r;
    asm("mov.b64 %0, {%1, %2};" : "=l"(r) : "f"(lo), "f"(hi));
    return r;
}
__device__ __forceinline__ void unpack2(unsigned long long v, float& lo, float& hi) {
    asm("mov.b64 {%0, %1}, %2;" : "=f"(lo), "=f"(hi) : "l"(v));
}
__device__ __forceinline__ unsigned long long fma2(unsigned long long a,
                                                   unsigned long long b,
                                                   unsigned long long c) {
    unsigned long long d;
    asm("fma.rn.f32x2 %0, %1, %2, %3;" : "=l"(d) : "l"(a), "l"(b), "l"(c));
    return d;
}
__device__ __forceinline__ float tanh_approx(float x) {
    float y;
    asm("tanh.approx.f32 %0, %1;" : "=f"(y) : "f"(x));
    return y;
}
__device__ __forceinline__ float silu_t(float t) {
    float th = tanh_approx(0.5f * t);
    return t * fmaf(0.5f, th, 0.5f);
}

// ---------------- SGEMM via FFMA2 (reads W_l/W_r directly) ----------------
#define BM 64
#define BN 64
#define BK 16
#define PAD 68

__global__ __launch_bounds__(256) void gemm_kernel(const float* __restrict__ q,
                                                   const float* __restrict__ Wl,
                                                   const float* __restrict__ Wr) {
    __shared__ float As[BK][PAD];
    __shared__ float Bs[BK][PAD];

    const int block_m = blockIdx.x * BM;
    const int block_n = blockIdx.y * BN;
    const int tid = threadIdx.x;
    const int tn = tid & 15;
    const int tm = tid >> 4;

    const int lrow  = tid >> 2;
    const int lcol4 = (tid & 3) << 2;

    // B source row pointer (Wcat row = block_n + lrow, constant across k0)
    const int brow = block_n + lrow;
    const float* wrow = (brow < H_CH) ? (Wl + brow * IN_CH)
                                      : (Wr + (brow - H_CH) * IN_CH);

    unsigned long long acc2[4][2];
#pragma unroll
    for (int i = 0; i < 4; i++) { acc2[i][0] = 0ULL; acc2[i][1] = 0ULL; }

#pragma unroll
    for (int k0 = 0; k0 < IN_CH; k0 += BK) {
        float4 av = make_float4(0.f, 0.f, 0.f, 0.f);
        int arow = block_m + lrow;
        if (arow < N_NODES)
            av = *reinterpret_cast<const float4*>(&q[arow * IN_CH + k0 + lcol4]);
        As[lcol4 + 0][lrow] = av.x;
        As[lcol4 + 1][lrow] = av.y;
        As[lcol4 + 2][lrow] = av.z;
        As[lcol4 + 3][lrow] = av.w;
        float4 bv = *reinterpret_cast<const float4*>(&wrow[k0 + lcol4]);
        Bs[lcol4 + 0][lrow] = bv.x;
        Bs[lcol4 + 1][lrow] = bv.y;
        Bs[lcol4 + 2][lrow] = bv.z;
        Bs[lcol4 + 3][lrow] = bv.w;
        __syncthreads();

#pragma unroll
        for (int kk = 0; kk < BK; kk++) {
            float4 a = *reinterpret_cast<const float4*>(&As[kk][tm << 2]);
            float4 b = *reinterpret_cast<const float4*>(&Bs[kk][tn << 2]);
            unsigned long long bp0 = pack2(b.x, b.y);
            unsigned long long bp1 = pack2(b.z, b.w);
            float ar[4] = {a.x, a.y, a.z, a.w};
#pragma unroll
            for (int i = 0; i < 4; i++) {
                unsigned long long ad = pack2(ar[i], ar[i]);
                acc2[i][0] = fma2(ad, bp0, acc2[i][0]);
                acc2[i][1] = fma2(ad, bp1, acc2[i][1]);
            }
        }
        __syncthreads();
    }

#pragma unroll
    for (int i = 0; i < 4; i++) {
        int row = block_m + (tm << 2) + i;
        if (row < N_NODES) {
            float o0, o1, o2, o3;
            unpack2(acc2[i][0], o0, o1);
            unpack2(acc2[i][1], o2, o3);
            *reinterpret_cast<float4*>(&d_g[row * NCAT + block_n + (tn << 2)]) =
                make_float4(o0, o1, o2, o3);
        }
    }
}

// ---------------- histogram of dst (4 edges/thread) ----------------
__global__ void hist_kernel(const int* __restrict__ ei) {
    int t = blockIdx.x * blockDim.x + threadIdx.x;
    int i4 = t * 4;
    if (i4 < N_EDGES) {
        int4 d = *reinterpret_cast<const int4*>(&ei[N_EDGES + i4]);
        atomicAdd(&d_count[d.x], 1);
        atomicAdd(&d_count[d.y], 1);
        atomicAdd(&d_count[d.z], 1);
        atomicAdd(&d_count[d.w], 1);
    }
}

// ---------------- scan phase A: per-block exclusive scan ----------------
#define SCANA_T 512
#define SCAN_NBLK ((N_NODES + SCANA_T - 1) / SCANA_T)   // 98

__global__ __launch_bounds__(SCANA_T) void scanA_kernel() {
    __shared__ int wt[16];
    int tid = threadIdx.x;
    int lane = tid & 31;
    int wid = tid >> 5;
    int idx = blockIdx.x * SCANA_T + tid;

    int v = (idx < N_NODES) ? d_count[idx] : 0;
    int ws = v;
#pragma unroll
    for (int off = 1; off < 32; off <<= 1) {
        int y = __shfl_up_sync(0xffffffffu, ws, off);
        if (lane >= off) ws += y;
    }
    if (lane == 31) wt[wid] = ws;
    __syncthreads();
    if (tid < 16) {
        int y = wt[tid];
#pragma unroll
        for (int off = 1; off < 16; off <<= 1) {
            int z = __shfl_up_sync(0x0000ffffu, y, off);
            if (tid >= off) y += z;
        }
        wt[tid] = y;
    }
    __syncthreads();
    int incl = ws + (wid ? wt[wid - 1] : 0);
    if (idx < N_NODES) d_start[idx] = incl - v;
    if (tid == SCANA_T - 1) d_bsum[blockIdx.x] = incl;
}

// ---------------- scan phase C (merged B+C): add block offset, fill cursor, re-zero count ----
__global__ __launch_bounds__(SCANA_T) void scanC_kernel() {
    __shared__ int off_s;
    int tid = threadIdx.x;
    int bx = blockIdx.x;
    if (tid < 32) {
        int partial = 0;
        for (int i = tid; i < bx; i += 32) partial += d_bsum[i];
#pragma unroll
        for (int off = 16; off > 0; off >>= 1)
            partial += __shfl_xor_sync(0xffffffffu, partial, off);
        if (tid == 0) off_s = partial;
    }
    __syncthreads();
    int idx = bx * SCANA_T + tid;
    if (idx < N_NODES) {
        int e = d_start[idx] + off_s;
        d_start[idx]  = e;
        d_cursor[idx] = e;
        d_count[idx]  = 0;      // restore invariant for next graph replay
    }
    if (bx == 0 && tid == 0) d_start[N_NODES] = N_EDGES;
}

// ---------------- scatter edges (4 edges/thread, bounds-guarded) ----------------
__global__ void scatter_kernel(const int* __restrict__ ei,
                               const float* __restrict__ envelope) {
    int t = blockIdx.x * blockDim.x + threadIdx.x;
    int i4 = t * 4;
    if (i4 < N_EDGES) {
        int4   s = *reinterpret_cast<const int4*>(&ei[i4]);
        int4   d = *reinterpret_cast<const int4*>(&ei[N_EDGES + i4]);
        float4 e = *reinterpret_cast<const float4*>(&envelope[i4]);
        int p0 = atomicAdd(&d_cursor[d.x], 1);
        if ((unsigned)p0 < N_EDGES) { d_src_sorted[p0] = s.x; d_env_sorted[p0] = e.x; }
        int p1 = atomicAdd(&d_cursor[d.y], 1);
        if ((unsigned)p1 < N_EDGES) { d_src_sorted[p1] = s.y; d_env_sorted[p1] = e.y; }
        int p2 = atomicAdd(&d_cursor[d.z], 1);
        if ((unsigned)p2 < N_EDGES) { d_src_sorted[p2] = s.z; d_env_sorted[p2] = e.z; }
        int p3 = atomicAdd(&d_cursor[d.w], 1);
        if ((unsigned)p3 < N_EDGES) { d_src_sorted[p3] = s.w; d_env_sorted[p3] = e.w; }
    }
}

// ---------------- per-node softmax + aggregation (warp/node, 4-edge unroll) ----------------
__global__ __launch_bounds__(256) void out_kernel(const float* __restrict__ attn_w,
                                                  float* __restrict__ out) {
    int warp_id = (blockIdx.x * blockDim.x + threadIdx.x) >> 5;
    if (warp_id >= N_NODES) return;
    int lane = threadIdx.x & 31;
    int n = warp_id;

    float4 gr = *reinterpret_cast<const float4*>(&d_g[n * NCAT + H_CH + (lane << 2)]);
    float4 aw = *reinterpret_cast<const float4*>(&attn_w[lane << 2]);

    float acc0 = 0.f, acc1 = 0.f, acc2 = 0.f, acc3 = 0.f;
    float denom = 0.f;

    int js = d_start[n];
    int je = d_start[n + 1];
    js = (js < 0) ? 0 : js;
    je = (je > N_EDGES) ? N_EDGES : je;

    for (int j = js; j < je; j += 4) {
        int j1 = j + 1, j2 = j + 2, j3 = j + 3;
        bool v1 = j1 < je, v2 = j2 < je, v3 = j3 < je;
        int jj1 = v1 ? j1 : j;
        int jj2 = v2 ? j2 : j;
        int jj3 = v3 ? j3 : j;

        int sA = d_src_sorted[j];
        int sB = d_src_sorted[jj1];
        int sC = d_src_sorted[jj2];
        int sD = d_src_sorted[jj3];
        float eA = d_env_sorted[j];
        float eB = d_env_sorted[jj1];
        float eC = d_env_sorted[jj2];
        float eD = d_env_sorted[jj3];

        float4 gA = *reinterpret_cast<const float4*>(&d_g[sA * NCAT + (lane << 2)]);
        float4 gB = *reinterpret_cast<const float4*>(&d_g[sB * NCAT + (lane << 2)]);
        float4 gC = *reinterpret_cast<const float4*>(&d_g[sC * NCAT + (lane << 2)]);
        float4 gD = *reinterpret_cast<const float4*>(&d_g[sD * NCAT + (lane << 2)]);

        float pA = silu_t(gA.x + gr.x) * aw.x + silu_t(gA.y + gr.y) * aw.y
                 + silu_t(gA.z + gr.z) * aw.z + silu_t(gA.w + gr.w) * aw.w;
        float pB = silu_t(gB.x + gr.x) * aw.x + silu_t(gB.y + gr.y) * aw.y
                 + silu_t(gB.z + gr.z) * aw.z + silu_t(gB.w + gr.w) * aw.w;
        float pC = silu_t(gC.x + gr.x) * aw.x + silu_t(gC.y + gr.y) * aw.y
                 + silu_t(gC.z + gr.z) * aw.z + silu_t(gC.w + gr.w) * aw.w;
        float pD = silu_t(gD.x + gr.x) * aw.x + silu_t(gD.y + gr.y) * aw.y
                 + silu_t(gD.z + gr.z) * aw.z + silu_t(gD.w + gr.w) * aw.w;

#pragma unroll
        for (int off = 16; off > 0; off >>= 1) {
            pA += __shfl_xor_sync(0xffffffffu, pA, off);
            pB += __shfl_xor_sync(0xffffffffu, pB, off);
            pC += __shfl_xor_sync(0xffffffffu, pC, off);
            pD += __shfl_xor_sync(0xffffffffu, pD, off);
        }

        float exA = __expf(pA) * (eA + 1e-7f);
        float exB = v1 ? (__expf(pB) * (eB + 1e-7f)) : 0.f;
        float exC = v2 ? (__expf(pC) * (eC + 1e-7f)) : 0.f;
        float exD = v3 ? (__expf(pD) * (eD + 1e-7f)) : 0.f;

        denom += (exA + exB) + (exC + exD);
        acc0 += exA * gA.x + exB * gB.x + exC * gC.x + exD * gD.x;
        acc1 += exA * gA.y + exB * gB.y + exC * gC.y + exD * gD.y;
        acc2 += exA * gA.z + exB * gB.z + exC * gC.z + exD * gD.z;
        acc3 += exA * gA.w + exB * gB.w + exC * gC.w + exD * gD.w;
    }

    float inv = (denom > 0.f) ? (1.f / denom) : 0.f;
    float4 o = make_float4(acc0 * inv, acc1 * inv, acc2 * inv, acc3 * inv);
    *reinterpret_cast<float4*>(&out[n * H_CH + (lane << 2)]) = o;
}

// ---------------- launch ----------------
extern "C" void kernel_launch(void* const* d_in, const int* in_sizes, int n_in,
                              void* d_out, int out_size) {
    const float* q        = (const float*)d_in[0];
    const float* envelope = (const float*)d_in[3];
    const float* W_l      = (const float*)d_in[4];
    const float* W_r      = (const float*)d_in[5];
    const float* attn_w   = (const float*)d_in[6];
    const int*   ei       = (const int*)d_in[7];
    float* out = (float*)d_out;

    // d_count is zero at entry (module init / re-zeroed by scanC each call)
    hist_kernel<<<(N_EDGES / 4 + 255) / 256, 256>>>(ei);
    scanA_kernel<<<SCAN_NBLK, SCANA_T>>>();
    scanC_kernel<<<SCAN_NBLK, SCANA_T>>>();
    scatter_kernel<<<(N_EDGES / 4 + 255) / 256, 256>>>(ei, envelope);

    dim3 ggrid((N_NODES + BM - 1) / BM, NCAT / BN);
    gemm_kernel<<<ggrid, 256>>>(q, W_l, W_r);

    int total_threads = N_NODES * 32;
    out_kernel<<<(total_threads + 255) / 256, 256>>>(attn_w, out);
}

// round 13
// speedup vs baseline: 1.1433x; 1.0231x over previous
#include <cuda_runtime.h>
#include <cuda_fp16.h>
#include <cstdint>

#define N_NODES 50000
#define N_EDGES 800000
#define IN_CH   128
#define H_CH    128
#define NCAT    256

// ---------------- device scratch ----------------
__device__ float  d_g[N_NODES * NCAT];         // row n: [g_l(128) | g_r(128)] f32
__device__ __half d_gl_h[N_NODES * H_CH];      // fp16 copy of g_l for gathers
__device__ int    d_count[N_NODES];            // invariant: zero at entry (scanC re-zeroes)
__device__ int    d_start[N_NODES + 1];
__device__ int    d_cursor[N_NODES];
__device__ int2   d_edge_sorted[N_EDGES];      // {src, env_bits}
__device__ int    d_bsum[128];

// ---------------- helpers ----------------
__device__ __forceinline__ unsigned long long pack2(float lo, float hi) {
    unsigned long long r;
    asm("mov.b64 %0, {%1, %2};" : "=l"(r) : "f"(lo), "f"(hi));
    return r;
}
__device__ __forceinline__ void unpack2(unsigned long long v, float& lo, float& hi) {
    asm("mov.b64 {%0, %1}, %2;" : "=f"(lo), "=f"(hi) : "l"(v));
}
__device__ __forceinline__ unsigned long long fma2(unsigned long long a,
                                                   unsigned long long b,
                                                   unsigned long long c) {
    unsigned long long d;
    asm("fma.rn.f32x2 %0, %1, %2, %3;" : "=l"(d) : "l"(a), "l"(b), "l"(c));
    return d;
}
__device__ __forceinline__ float tanh_approx(float x) {
    float y;
    asm("tanh.approx.f32 %0, %1;" : "=f"(y) : "f"(x));
    return y;
}
__device__ __forceinline__ float silu_t(float t) {
    float th = tanh_approx(0.5f * t);
    return t * fmaf(0.5f, th, 0.5f);
}

// ---------------- SGEMM via FFMA2 (reads W_l/W_r directly; dual epilogue) ----------------
#define BM 64
#define BN 64
#define BK 16
#define PAD 68

__global__ __launch_bounds__(256) void gemm_kernel(const float* __restrict__ q,
                                                   const float* __restrict__ Wl,
                                                   const float* __restrict__ Wr) {
    __shared__ float As[BK][PAD];
    __shared__ float Bs[BK][PAD];

    const int block_m = blockIdx.x * BM;
    const int block_n = blockIdx.y * BN;
    const int tid = threadIdx.x;
    const int tn = tid & 15;
    const int tm = tid >> 4;

    const int lrow  = tid >> 2;
    const int lcol4 = (tid & 3) << 2;

    const int brow = block_n + lrow;
    const float* wrow = (brow < H_CH) ? (Wl + brow * IN_CH)
                                      : (Wr + (brow - H_CH) * IN_CH);

    unsigned long long acc2[4][2];
#pragma unroll
    for (int i = 0; i < 4; i++) { acc2[i][0] = 0ULL; acc2[i][1] = 0ULL; }

#pragma unroll
    for (int k0 = 0; k0 < IN_CH; k0 += BK) {
        float4 av = make_float4(0.f, 0.f, 0.f, 0.f);
        int arow = block_m + lrow;
        if (arow < N_NODES)
            av = *reinterpret_cast<const float4*>(&q[arow * IN_CH + k0 + lcol4]);
        As[lcol4 + 0][lrow] = av.x;
        As[lcol4 + 1][lrow] = av.y;
        As[lcol4 + 2][lrow] = av.z;
        As[lcol4 + 3][lrow] = av.w;
        float4 bv = *reinterpret_cast<const float4*>(&wrow[k0 + lcol4]);
        Bs[lcol4 + 0][lrow] = bv.x;
        Bs[lcol4 + 1][lrow] = bv.y;
        Bs[lcol4 + 2][lrow] = bv.z;
        Bs[lcol4 + 3][lrow] = bv.w;
        __syncthreads();

#pragma unroll
        for (int kk = 0; kk < BK; kk++) {
            float4 a = *reinterpret_cast<const float4*>(&As[kk][tm << 2]);
            float4 b = *reinterpret_cast<const float4*>(&Bs[kk][tn << 2]);
            unsigned long long bp0 = pack2(b.x, b.y);
            unsigned long long bp1 = pack2(b.z, b.w);
            float ar[4] = {a.x, a.y, a.z, a.w};
#pragma unroll
            for (int i = 0; i < 4; i++) {
                unsigned long long ad = pack2(ar[i], ar[i]);
                acc2[i][0] = fma2(ad, bp0, acc2[i][0]);
                acc2[i][1] = fma2(ad, bp1, acc2[i][1]);
            }
        }
        __syncthreads();
    }

#pragma unroll
    for (int i = 0; i < 4; i++) {
        int row = block_m + (tm << 2) + i;
        if (row < N_NODES) {
            float o0, o1, o2, o3;
            unpack2(acc2[i][0], o0, o1);
            unpack2(acc2[i][1], o2, o3);
            *reinterpret_cast<float4*>(&d_g[row * NCAT + block_n + (tn << 2)]) =
                make_float4(o0, o1, o2, o3);
            if (block_n < H_CH) {   // g_l columns: also write fp16 gather copy
                __half2 h01 = __floats2half2_rn(o0, o1);
                __half2 h23 = __floats2half2_rn(o2, o3);
                __half2* hp = reinterpret_cast<__half2*>(
                    &d_gl_h[row * H_CH + block_n + (tn << 2)]);
                hp[0] = h01;
                hp[1] = h23;
            }
        }
    }
}

// ---------------- histogram of dst (8 edges/thread) ----------------
__global__ void hist_kernel(const int* __restrict__ ei) {
    int t = blockIdx.x * blockDim.x + threadIdx.x;
    int i8 = t * 8;
    if (i8 < N_EDGES) {
        int4 d0 = *reinterpret_cast<const int4*>(&ei[N_EDGES + i8]);
        int4 d1 = *reinterpret_cast<const int4*>(&ei[N_EDGES + i8 + 4]);
        atomicAdd(&d_count[d0.x], 1);
        atomicAdd(&d_count[d0.y], 1);
        atomicAdd(&d_count[d0.z], 1);
        atomicAdd(&d_count[d0.w], 1);
        atomicAdd(&d_count[d1.x], 1);
        atomicAdd(&d_count[d1.y], 1);
        atomicAdd(&d_count[d1.z], 1);
        atomicAdd(&d_count[d1.w], 1);
    }
}

// ---------------- scan phase A: per-block exclusive scan ----------------
#define SCANA_T 512
#define SCAN_NBLK ((N_NODES + SCANA_T - 1) / SCANA_T)   // 98

__global__ __launch_bounds__(SCANA_T) void scanA_kernel() {
    __shared__ int wt[16];
    int tid = threadIdx.x;
    int lane = tid & 31;
    int wid = tid >> 5;
    int idx = blockIdx.x * SCANA_T + tid;

    int v = (idx < N_NODES) ? d_count[idx] : 0;
    int ws = v;
#pragma unroll
    for (int off = 1; off < 32; off <<= 1) {
        int y = __shfl_up_sync(0xffffffffu, ws, off);
        if (lane >= off) ws += y;
    }
    if (lane == 31) wt[wid] = ws;
    __syncthreads();
    if (tid < 16) {
        int y = wt[tid];
#pragma unroll
        for (int off = 1; off < 16; off <<= 1) {
            int z = __shfl_up_sync(0x0000ffffu, y, off);
            if (tid >= off) y += z;
        }
        wt[tid] = y;
    }
    __syncthreads();
    int incl = ws + (wid ? wt[wid - 1] : 0);
    if (idx < N_NODES) d_start[idx] = incl - v;
    if (tid == SCANA_T - 1) d_bsum[blockIdx.x] = incl;
}

// ---------------- scan phase C: add block offset, fill cursor, re-zero count ----------------
__global__ __launch_bounds__(SCANA_T) void scanC_kernel() {
    __shared__ int off_s;
    int tid = threadIdx.x;
    int bx = blockIdx.x;
    if (tid < 32) {
        int partial = 0;
        for (int i = tid; i < bx; i += 32) partial += d_bsum[i];
#pragma unroll
        for (int off = 16; off > 0; off >>= 1)
            partial += __shfl_xor_sync(0xffffffffu, partial, off);
        if (tid == 0) off_s = partial;
    }
    __syncthreads();
    int idx = bx * SCANA_T + tid;
    if (idx < N_NODES) {
        int e = d_start[idx] + off_s;
        d_start[idx]  = e;
        d_cursor[idx] = e;
        d_count[idx]  = 0;
    }
    if (bx == 0 && tid == 0) d_start[N_NODES] = N_EDGES;
}

// ---------------- scatter edges (8 edges/thread, int2 records, bounds-guarded) ----------------
__global__ void scatter_kernel(const int* __restrict__ ei,
                               const float* __restrict__ envelope) {
    int t = blockIdx.x * blockDim.x + threadIdx.x;
    int i8 = t * 8;
    if (i8 < N_EDGES) {
        int4   s0 = *reinterpret_cast<const int4*>(&ei[i8]);
        int4   s1 = *reinterpret_cast<const int4*>(&ei[i8 + 4]);
        int4   d0 = *reinterpret_cast<const int4*>(&ei[N_EDGES + i8]);
        int4   d1 = *reinterpret_cast<const int4*>(&ei[N_EDGES + i8 + 4]);
        float4 e0 = *reinterpret_cast<const float4*>(&envelope[i8]);
        float4 e1 = *reinterpret_cast<const float4*>(&envelope[i8 + 4]);

        int p;
        p = atomicAdd(&d_cursor[d0.x], 1);
        if ((unsigned)p < N_EDGES) d_edge_sorted[p] = make_int2(s0.x, __float_as_int(e0.x));
        p = atomicAdd(&d_cursor[d0.y], 1);
        if ((unsigned)p < N_EDGES) d_edge_sorted[p] = make_int2(s0.y, __float_as_int(e0.y));
        p = atomicAdd(&d_cursor[d0.z], 1);
        if ((unsigned)p < N_EDGES) d_edge_sorted[p] = make_int2(s0.z, __float_as_int(e0.z));
        p = atomicAdd(&d_cursor[d0.w], 1);
        if ((unsigned)p < N_EDGES) d_edge_sorted[p] = make_int2(s0.w, __float_as_int(e0.w));
        p = atomicAdd(&d_cursor[d1.x], 1);
        if ((unsigned)p < N_EDGES) d_edge_sorted[p] = make_int2(s1.x, __float_as_int(e1.x));
        p = atomicAdd(&d_cursor[d1.y], 1);
        if ((unsigned)p < N_EDGES) d_edge_sorted[p] = make_int2(s1.y, __float_as_int(e1.y));
        p = atomicAdd(&d_cursor[d1.z], 1);
        if ((unsigned)p < N_EDGES) d_edge_sorted[p] = make_int2(s1.z, __float_as_int(e1.z));
        p = atomicAdd(&d_cursor[d1.w], 1);
        if ((unsigned)p < N_EDGES) d_edge_sorted[p] = make_int2(s1.w, __float_as_int(e1.w));
    }
}

// ---------------- per-node softmax + aggregation (warp/node, 4-edge unroll, fp16 gather) ----
__device__ __forceinline__ void gather4(int src, int lane, float4& g) {
    uint2 raw = *reinterpret_cast<const uint2*>(&d_gl_h[src * H_CH + (lane << 2)]);
    float2 f0 = __half22float2(*reinterpret_cast<__half2*>(&raw.x));
    float2 f1 = __half22float2(*reinterpret_cast<__half2*>(&raw.y));
    g = make_float4(f0.x, f0.y, f1.x, f1.y);
}

__global__ __launch_bounds__(256) void out_kernel(const float* __restrict__ attn_w,
                                                  float* __restrict__ out) {
    int warp_id = (blockIdx.x * blockDim.x + threadIdx.x) >> 5;
    if (warp_id >= N_NODES) return;
    int lane = threadIdx.x & 31;
    int n = warp_id;

    float4 gr = *reinterpret_cast<const float4*>(&d_g[n * NCAT + H_CH + (lane << 2)]);
    float4 aw = *reinterpret_cast<const float4*>(&attn_w[lane << 2]);

    float acc0 = 0.f, acc1 = 0.f, acc2 = 0.f, acc3 = 0.f;
    float denom = 0.f;

    int js = d_start[n];
    int je = d_start[n + 1];
    js = (js < 0) ? 0 : js;
    je = (je > N_EDGES) ? N_EDGES : je;

    for (int j = js; j < je; j += 4) {
        int j1 = j + 1, j2 = j + 2, j3 = j + 3;
        bool v1 = j1 < je, v2 = j2 < je, v3 = j3 < je;
        int2 eA = d_edge_sorted[j];
        int2 eB = d_edge_sorted[v1 ? j1 : j];
        int2 eC = d_edge_sorted[v2 ? j2 : j];
        int2 eD = d_edge_sorted[v3 ? j3 : j];

        float4 gA, gB, gC, gD;
        gather4(eA.x, lane, gA);
        gather4(eB.x, lane, gB);
        gather4(eC.x, lane, gC);
        gather4(eD.x, lane, gD);

        float pA = silu_t(gA.x + gr.x) * aw.x + silu_t(gA.y + gr.y) * aw.y
                 + silu_t(gA.z + gr.z) * aw.z + silu_t(gA.w + gr.w) * aw.w;
        float pB = silu_t(gB.x + gr.x) * aw.x + silu_t(gB.y + gr.y) * aw.y
                 + silu_t(gB.z + gr.z) * aw.z + silu_t(gB.w + gr.w) * aw.w;
        float pC = silu_t(gC.x + gr.x) * aw.x + silu_t(gC.y + gr.y) * aw.y
                 + silu_t(gC.z + gr.z) * aw.z + silu_t(gC.w + gr.w) * aw.w;
        float pD = silu_t(gD.x + gr.x) * aw.x + silu_t(gD.y + gr.y) * aw.y
                 + silu_t(gD.z + gr.z) * aw.z + silu_t(gD.w + gr.w) * aw.w;

#pragma unroll
        for (int off = 16; off > 0; off >>= 1) {
            pA += __shfl_xor_sync(0xffffffffu, pA, off);
            pB += __shfl_xor_sync(0xffffffffu, pB, off);
            pC += __shfl_xor_sync(0xffffffffu, pC, off);
            pD += __shfl_xor_sync(0xffffffffu, pD, off);
        }

        float exA = __expf(pA) * (__int_as_float(eA.y) + 1e-7f);
        float exB = v1 ? (__expf(pB) * (__int_as_float(eB.y) + 1e-7f)) : 0.f;
        float exC = v2 ? (__expf(pC) * (__int_as_float(eC.y) + 1e-7f)) : 0.f;
        float exD = v3 ? (__expf(pD) * (__int_as_float(eD.y) + 1e-7f)) : 0.f;

        denom += (exA + exB) + (exC + exD);
        acc0 += exA * gA.x + exB * gB.x + exC * gC.x + exD * gD.x;
        acc1 += exA * gA.y + exB * gB.y + exC * gC.y + exD * gD.y;
        acc2 += exA * gA.z + exB * gB.z + exC * gC.z + exD * gD.z;
        acc3 += exA * gA.w + exB * gB.w + exC * gC.w + exD * gD.w;
    }

    float inv = (denom > 0.f) ? (1.f / denom) : 0.f;
    float4 o = make_float4(acc0 * inv, acc1 * inv, acc2 * inv, acc3 * inv);
    *reinterpret_cast<float4*>(&out[n * H_CH + (lane << 2)]) = o;
}

// ---------------- launch ----------------
extern "C" void kernel_launch(void* const* d_in, const int* in_sizes, int n_in,
                              void* d_out, int out_size) {
    const float* q        = (const float*)d_in[0];
    const float* envelope = (const float*)d_in[3];
    const float* W_l      = (const float*)d_in[4];
    const float* W_r      = (const float*)d_in[5];
    const float* attn_w   = (const float*)d_in[6];
    const int*   ei       = (const int*)d_in[7];
    float* out = (float*)d_out;

    hist_kernel<<<(N_EDGES / 8 + 255) / 256, 256>>>(ei);
    scanA_kernel<<<SCAN_NBLK, SCANA_T>>>();
    scanC_kernel<<<SCAN_NBLK, SCANA_T>>>();
    scatter_kernel<<<(N_EDGES / 8 + 255) / 256, 256>>>(ei, envelope);

    dim3 ggrid((N_NODES + BM - 1) / BM, NCAT / BN);
    gemm_kernel<<<ggrid, 256>>>(q, W_l, W_r);

    int total_threads = N_NODES * 32;
    out_kernel<<<(total_threads + 255) / 256, 256>>>(attn_w, out);
}